// round 1
// baseline (speedup 1.0000x reference)
#include <cuda_runtime.h>
#include <math.h>

#define C_IN   768
#define HF     14
#define P      196
#define A      9
#define NA     1764
#define NSORT  2048
#define NPRE   1000
#define NOUT   300
#define IMGSZ  224.0f
#define NMS_TH 0.7f
#define MINSZ  16.0f
#define BBOX_CLIP 4.135166556742356f

// conv tiling
#define KSPLIT 6
#define KPER   128   // 768/6 input channels per block
#define KC     16    // smem chunk of input channels
#define NTILE  16
#define NTILES 48    // 768/16

// ---------------- device scratch (no allocations allowed) ----------------
__device__ float g_part[KSPLIT][P * C_IN];
__device__ float g_x[P * C_IN];
__device__ float g_key[NSORT];
__device__ int   g_sidx[NSORT];
__device__ float g_boxes[NA * 4];
__device__ float g_tbox[NPRE * 4];
__device__ float g_tprob[NPRE];
__device__ int   g_tvalid[NPRE];
__device__ unsigned g_mask[NPRE * 32];

// base anchors, order a = ratio_idx*3 + scale_idx, ratios (0.5,1,2), scales (128,256,512)
// values = round(±w/2, ±h/2) with round-half-even, precomputed (no ties near .5)
__constant__ float c_base[9][4] = {
    {-91.f,  -45.f,  91.f,  45.f},
    {-181.f, -91.f,  181.f, 91.f},
    {-362.f, -181.f, 362.f, 181.f},
    {-64.f,  -64.f,  64.f,  64.f},
    {-128.f, -128.f, 128.f, 128.f},
    {-256.f, -256.f, 256.f, 256.f},
    {-45.f,  -91.f,  45.f,  91.f},
    {-91.f,  -181.f, 91.f,  181.f},
    {-181.f, -362.f, 181.f, 362.f}};

// ---------------- K1: 3x3 conv partial sums (implicit GEMM) ----------------
// grid = NTILES*KSPLIT = 288 blocks, 256 threads.
// block: 16 out-channels x 196 pixels, over 128 input channels (one k-split).
// thread: 4 pixels x 4 out-channels register tile.
__global__ void __launch_bounds__(256) conv_part(const float* __restrict__ feat,
                                                 const float* __restrict__ wconv) {
    int bx    = blockIdx.x;
    int ntile = bx % NTILES;
    int ks    = bx / NTILES;
    int n0    = ntile * NTILE;
    int cbase0 = ks * KPER;
    int tid = threadIdx.x;
    int tx  = tid & 63;   // pixel group
    int ty  = tid >> 6;   // out-channel quad (0..3)

    __shared__ __align__(16) float sF[KC][256];       // padded 16x16 per channel
    __shared__ __align__(16) float sW[KC][9][NTILE];

    float acc[4][4];
#pragma unroll
    for (int i = 0; i < 4; i++)
#pragma unroll
        for (int j = 0; j < 4; j++) acc[i][j] = 0.f;

    int pb[4];
#pragma unroll
    for (int i = 0; i < 4; i++) {
        int p = tx + i * 64;
        pb[i] = (p < P) ? ((p / HF) * 16 + (p % HF)) : 0;  // fallback 0 (results discarded)
    }

    for (int cc = 0; cc < KPER; cc += KC) {
        int cbase = cbase0 + cc;
        __syncthreads();
        // zero feat tile (handles SAME padding border)
        for (int i = tid; i < KC * 256; i += 256) ((float*)sF)[i] = 0.f;
        __syncthreads();
        // fill interior: sF[c][(y+1)*16 + (x+1)]
        for (int i = tid; i < KC * P; i += 256) {
            int c = i / P, p = i - c * P;
            sF[c][(p / HF) * 16 + (p % HF) + 17] = feat[(size_t)(cbase + c) * P + p];
        }
        // weights: per out-channel, 16*9=144 contiguous floats
        for (int i = tid; i < KC * 9 * NTILE; i += 256) {
            int n_l = i / (KC * 9);
            int rem = i - n_l * (KC * 9);
            int c = rem / 9, k = rem - c * 9;
            sW[c][k][n_l] = wconv[(size_t)(n0 + n_l) * (C_IN * 9) + (size_t)cbase * 9 + rem];
        }
        __syncthreads();

#pragma unroll 4
        for (int c = 0; c < KC; c++) {
#pragma unroll
            for (int k = 0; k < 9; k++) {
                int off = (k / 3) * 16 + (k % 3);
                const float4 wv = *(const float4*)&sW[c][k][ty * 4];
                float f0 = sF[c][pb[0] + off];
                float f1 = sF[c][pb[1] + off];
                float f2 = sF[c][pb[2] + off];
                float f3 = sF[c][pb[3] + off];
                acc[0][0] += f0 * wv.x; acc[0][1] += f0 * wv.y; acc[0][2] += f0 * wv.z; acc[0][3] += f0 * wv.w;
                acc[1][0] += f1 * wv.x; acc[1][1] += f1 * wv.y; acc[1][2] += f1 * wv.z; acc[1][3] += f1 * wv.w;
                acc[2][0] += f2 * wv.x; acc[2][1] += f2 * wv.y; acc[2][2] += f2 * wv.z; acc[2][3] += f2 * wv.w;
                acc[3][0] += f3 * wv.x; acc[3][1] += f3 * wv.y; acc[3][2] += f3 * wv.z; acc[3][3] += f3 * wv.w;
            }
        }
    }

#pragma unroll
    for (int i = 0; i < 4; i++) {
        int p = tx + i * 64;
        if (p < P) {
            *(float4*)&g_part[ks][(size_t)p * C_IN + n0 + ty * 4] =
                make_float4(acc[i][0], acc[i][1], acc[i][2], acc[i][3]);
        }
    }
}

// ---------------- K1b: sum partials + bias + relu ----------------
__global__ void relu_sum(const float* __restrict__ bconv) {
    int i = blockIdx.x * 256 + threadIdx.x;
    if (i < P * C_IN) {
        float s = 0.f;
#pragma unroll
        for (int k = 0; k < KSPLIT; k++) s += g_part[k][i];
        s += bconv[i % C_IN];
        g_x[i] = fmaxf(s, 0.f);
    }
}

// ---------------- K2: cls/reg heads + box decode ----------------
// one warp per (pixel, anchor)
__global__ void heads(const float* __restrict__ wcls, const float* __restrict__ bcls,
                      const float* __restrict__ wreg, const float* __restrict__ breg) {
    int gw   = (blockIdx.x * blockDim.x + threadIdx.x) >> 5;
    int lane = threadIdx.x & 31;
    if (gw >= NA) return;
    int p = gw / A, a = gw - p * A;

    const float* xr = &g_x[(size_t)p * C_IN];
    const float* wc = &wcls[(size_t)a * C_IN];
    const float* w0 = &wreg[(size_t)(a * 4 + 0) * C_IN];
    const float* w1 = &wreg[(size_t)(a * 4 + 1) * C_IN];
    const float* w2 = &wreg[(size_t)(a * 4 + 2) * C_IN];
    const float* w3 = &wreg[(size_t)(a * 4 + 3) * C_IN];

    float a0 = 0.f, a1 = 0.f, a2 = 0.f, a3 = 0.f, a4 = 0.f;
    for (int c = lane; c < C_IN; c += 32) {
        float xv = xr[c];
        a0 += xv * wc[c];
        a1 += xv * w0[c];
        a2 += xv * w1[c];
        a3 += xv * w2[c];
        a4 += xv * w3[c];
    }
#pragma unroll
    for (int o = 16; o > 0; o >>= 1) {
        a0 += __shfl_down_sync(0xffffffffu, a0, o);
        a1 += __shfl_down_sync(0xffffffffu, a1, o);
        a2 += __shfl_down_sync(0xffffffffu, a2, o);
        a3 += __shfl_down_sync(0xffffffffu, a3, o);
        a4 += __shfl_down_sync(0xffffffffu, a4, o);
    }
    if (lane == 0) {
        float s  = a0 + bcls[a];
        float dx = a1 + breg[a * 4 + 0];
        float dy = a2 + breg[a * 4 + 1];
        float dw = fminf(a3 + breg[a * 4 + 2], BBOX_CLIP);
        float dh = fminf(a4 + breg[a * 4 + 3], BBOX_CLIP);

        int y = p / HF, x = p - y * HF;
        float sx = x * 16.f, sy = y * 16.f;
        float ax0 = sx + c_base[a][0], ay0 = sy + c_base[a][1];
        float ax1 = sx + c_base[a][2], ay1 = sy + c_base[a][3];
        float aw = ax1 - ax0, ah = ay1 - ay0;
        float cx = ax0 + 0.5f * aw, cy = ay0 + 0.5f * ah;
        float pcx = dx * aw + cx, pcy = dy * ah + cy;
        float pw = expf(dw) * aw, ph = expf(dh) * ah;

        g_boxes[gw * 4 + 0] = pcx - 0.5f * pw;
        g_boxes[gw * 4 + 1] = pcy - 0.5f * ph;
        g_boxes[gw * 4 + 2] = pcx + 0.5f * pw;
        g_boxes[gw * 4 + 3] = pcy + 0.5f * ph;
        // sort key: sigmoid prob in fp32 (matches reference tie granularity)
        g_key[gw] = __fdiv_rn(1.f, 1.f + expf(-s));
    }
}

// ---------------- K3: bitonic sort (descending, tie -> lower index first) ----------------
__global__ void __launch_bounds__(1024) sortk() {
    __shared__ float key[NSORT];
    __shared__ int   idx[NSORT];
    int tid = threadIdx.x;
    for (int i = tid; i < NSORT; i += 1024) {
        key[i] = (i < NA) ? g_key[i] : -3.0e38f;
        idx[i] = i;
    }
    __syncthreads();
    for (int k = 2; k <= NSORT; k <<= 1) {
        for (int j = k >> 1; j > 0; j >>= 1) {
            for (int m = tid; m < NSORT / 2; m += 1024) {
                int i  = ((m & ~(j - 1)) << 1) | (m & (j - 1));
                int p2 = i | j;
                bool desc = ((i & k) == 0);
                float ka = key[i], kb = key[p2];
                int   ia = idx[i], ib = idx[p2];
                bool aLess = (ka < kb) || (ka == kb && ia > ib);
                if (aLess == desc) {
                    key[i] = kb; key[p2] = ka;
                    idx[i] = ib; idx[p2] = ia;
                }
            }
            __syncthreads();
        }
    }
    for (int i = tid; i < NSORT; i += 1024) {
        g_key[i]  = key[i];
        g_sidx[i] = idx[i];
    }
}

// ---------------- K4a: gather + clip + validity for top-1000 ----------------
__global__ void prep() {
    int i = blockIdx.x * blockDim.x + threadIdx.x;
    if (i >= NPRE) return;
    int id = g_sidx[i];
    float x1 = g_boxes[id * 4 + 0], y1 = g_boxes[id * 4 + 1];
    float x2 = g_boxes[id * 4 + 2], y2 = g_boxes[id * 4 + 3];
    x1 = fminf(fmaxf(x1, 0.f), IMGSZ);
    y1 = fminf(fmaxf(y1, 0.f), IMGSZ);
    x2 = fminf(fmaxf(x2, 0.f), IMGSZ);
    y2 = fminf(fmaxf(y2, 0.f), IMGSZ);
    g_tbox[i * 4 + 0] = x1; g_tbox[i * 4 + 1] = y1;
    g_tbox[i * 4 + 2] = x2; g_tbox[i * 4 + 3] = y2;
    g_tvalid[i] = ((x2 - x1) >= MINSZ) && ((y2 - y1) >= MINSZ);
    g_tprob[i]  = g_key[i];
}

// ---------------- K4b: IoU suppression bitmask ----------------
// grid 125 blocks of (32,8): 8 rows per block, 32 mask words per row
__global__ void __launch_bounds__(256) nms_mask() {
    __shared__ float sb[NPRE * 4];
    int ltid = threadIdx.y * 32 + threadIdx.x;
    for (int t = ltid; t < NPRE * 4; t += 256) sb[t] = g_tbox[t];
    __syncthreads();

    int i  = blockIdx.x * 8 + threadIdx.y;
    int tx = threadIdx.x;
    float ix1 = sb[i * 4 + 0], iy1 = sb[i * 4 + 1];
    float ix2 = sb[i * 4 + 2], iy2 = sb[i * 4 + 3];
    float iarea = (ix2 - ix1) * (iy2 - iy1);
    unsigned mword = 0;
    int jbase = tx * 32;
#pragma unroll 4
    for (int b = 0; b < 32; b++) {
        int j = jbase + b;
        if (j > i && j < NPRE) {
            float jx1 = sb[j * 4 + 0], jy1 = sb[j * 4 + 1];
            float jx2 = sb[j * 4 + 2], jy2 = sb[j * 4 + 3];
            float ww = fmaxf(0.f, fminf(ix2, jx2) - fmaxf(ix1, jx1));
            float hh = fmaxf(0.f, fminf(iy2, jy2) - fmaxf(iy1, jy1));
            float inter = ww * hh;
            float uni = iarea + (jx2 - jx1) * (jy2 - jy1) - inter;
            float iou = (uni > 0.f) ? __fdiv_rn(inter, uni) : 0.f;
            if (iou > NMS_TH) mword |= (1u << b);
        }
    }
    g_mask[i * 32 + tx] = mword;
}

// ---------------- K5: serial NMS scan + output compaction ----------------
// single block; mask staged in dynamic smem; warp 0 scans with removed-bitset in regs
__global__ void nms_scan(float* __restrict__ out) {
    extern __shared__ unsigned sm[];
    unsigned* smask = sm;                 // 32000 words
    int* svalid = (int*)(sm + NPRE * 32); // 1000 ints
    int tid = threadIdx.x;
    for (int t = tid; t < NPRE * 32; t += blockDim.x) smask[t] = g_mask[t];
    for (int t = tid; t < NPRE; t += blockDim.x) svalid[t] = g_tvalid[t];
    for (int t = tid; t < NOUT * 5; t += blockDim.x) out[t] = 0.f;
    __syncthreads();

    if (tid < 32) {
        int lane = tid;
        unsigned removed = 0;
        int count = 0;
        unsigned rown = smask[lane];  // prefetch row 0
        for (int i = 0; i < NPRE; i++) {
            unsigned row = rown;
            rown = (i + 1 < NPRE) ? smask[(i + 1) * 32 + lane] : 0u;
            unsigned rm = __shfl_sync(0xffffffffu, removed, i >> 5);
            bool kept = svalid[i] && !((rm >> (i & 31)) & 1u);
            if (kept) {
                removed |= row;
                if (lane < 4) out[count * 4 + lane] = g_tbox[i * 4 + lane];
                if (lane == 4) out[NOUT * 4 + count] = g_tprob[i];
                count++;
                if (count == NOUT) break;
            }
        }
    }
}

// ---------------- host launcher ----------------
extern "C" void kernel_launch(void* const* d_in, const int* in_sizes, int n_in,
                              void* d_out, int out_size) {
    const float* feature = (const float*)d_in[1];
    const float* w_conv  = (const float*)d_in[2];
    const float* b_conv  = (const float*)d_in[3];
    const float* w_cls   = (const float*)d_in[4];
    const float* b_cls   = (const float*)d_in[5];
    const float* w_reg   = (const float*)d_in[6];
    const float* b_reg   = (const float*)d_in[7];
    float* out = (float*)d_out;

    // skip CLS token: feature[:,1:,:] reinterpreted as NCHW (768,14,14)
    const float* feat = feature + C_IN;

    conv_part<<<NTILES * KSPLIT, 256>>>(feat, w_conv);
    relu_sum<<<(P * C_IN + 255) / 256, 256>>>(b_conv);
    heads<<<(NA * 32 + 255) / 256, 256>>>(w_cls, b_cls, w_reg, b_reg);
    sortk<<<1, 1024>>>();
    prep<<<(NPRE + 255) / 256, 256>>>();
    nms_mask<<<NPRE / 8, dim3(32, 8)>>>();

    int smem_bytes = NPRE * 32 * 4 + NPRE * 4;
    cudaFuncSetAttribute(nms_scan, cudaFuncAttributeMaxDynamicSharedMemorySize, smem_bytes);
    nms_scan<<<1, 128, smem_bytes>>>(out);
}

// round 2
// speedup vs baseline: 1.2350x; 1.2350x over previous
#include <cuda_runtime.h>
#include <math.h>

#define C_IN   768
#define HF     14
#define P      196
#define A      9
#define NA     1764
#define NPRE   1000
#define NOUT   300
#define IMGSZ  224.0f
#define NMS_TH 0.7f
#define MINSZ  16.0f
#define BBOX_CLIP 4.135166556742356f

// conv tiling: 144 blocks = 1 wave on 148 SMs
#define KSPLIT 6
#define KPER   128   // 768/6 input channels per block
#define KC     16    // smem chunk of input channels
#define NTILE  32    // out channels per block
#define NTILES 24    // 768/32

typedef unsigned long long ull;

// packed fp32x2 FMA (FFMA2) — 2x fp32 FMA throughput, exact fp32 per lane
#define FMA2(d, a, b) asm("fma.rn.f32x2 %0, %1, %2, %3;" : "=l"(d) : "l"(a), "l"(b), "l"(d))
#define PACK2(out, lo, hi) asm("mov.b64 %0, {%1, %2};" : "=l"(out) : "r"(__float_as_uint(lo)), "r"(__float_as_uint(hi)))

// ---------------- device scratch ----------------
__device__ float g_part[KSPLIT][P * C_IN];
__device__ float g_x[P * C_IN];
__device__ float g_key[NA];
__device__ float g_boxes[NA * 4];
__device__ float g_tbox[NPRE * 4];
__device__ float g_tprob[NPRE];
__device__ int   g_tvalid[NPRE];
__device__ unsigned g_mask[NPRE * 32];

// base anchors: a = ratio_idx*3 + scale_idx, ratios (0.5,1,2), scales (128,256,512)
__constant__ float c_base[9][4] = {
    {-91.f,  -45.f,  91.f,  45.f},
    {-181.f, -91.f,  181.f, 91.f},
    {-362.f, -181.f, 362.f, 181.f},
    {-64.f,  -64.f,  64.f,  64.f},
    {-128.f, -128.f, 128.f, 128.f},
    {-256.f, -256.f, 256.f, 256.f},
    {-45.f,  -91.f,  45.f,  91.f},
    {-91.f,  -181.f, 91.f,  181.f},
    {-181.f, -362.f, 181.f, 362.f}};

// ---------------- K1: 3x3 conv partial sums (implicit GEMM, FFMA2) ----------------
// 144 blocks x 256 threads; block = 32 out-ch x 196 px x 128 in-ch (one K-split).
// thread = 4 pixels x 8 out-channels (4 f32x2 pairs) register tile.
__global__ void __launch_bounds__(256) conv_part(const float* __restrict__ feat,
                                                 const float* __restrict__ wconv) {
    int bx     = blockIdx.x;
    int ntile  = bx % NTILES;
    int ks     = bx / NTILES;
    int n0     = ntile * NTILE;
    int cbase0 = ks * KPER;
    int tid = threadIdx.x;
    int tx  = tid & 63;   // pixel group
    int ty  = tid >> 6;   // out-channel octet (0..3)

    __shared__ __align__(16) float sF[KC][256];       // 16x16 padded tile per channel
    __shared__ __align__(16) float sW[KC][9][NTILE];

    ull acc[4][4];  // [pixel][och-pair]
#pragma unroll
    for (int i = 0; i < 4; i++)
#pragma unroll
        for (int j = 0; j < 4; j++) acc[i][j] = 0ULL;

    int pb[4];
#pragma unroll
    for (int i = 0; i < 4; i++) {
        int p = tx + i * 64;
        pb[i] = (p < P) ? ((p / HF) * 16 + (p % HF)) : 0;  // fallback (discarded)
    }

    for (int cc = 0; cc < KPER; cc += KC) {
        int cbase = cbase0 + cc;
        __syncthreads();
        for (int i = tid; i < KC * 256; i += 256) ((float*)sF)[i] = 0.f;
        __syncthreads();
        for (int i = tid; i < KC * P; i += 256) {
            int c = i / P, p = i - c * P;
            sF[c][(p / HF) * 16 + (p % HF) + 17] = feat[(size_t)(cbase + c) * P + p];
        }
        for (int i = tid; i < KC * 9 * NTILE; i += 256) {
            int n_l = i / (KC * 9);
            int rem = i - n_l * (KC * 9);
            int c = rem / 9, k = rem - c * 9;
            sW[c][k][n_l] = wconv[(size_t)(n0 + n_l) * (C_IN * 9) + (size_t)cbase * 9 + rem];
        }
        __syncthreads();

#pragma unroll 2
        for (int c = 0; c < KC; c++) {
#pragma unroll
            for (int k = 0; k < 9; k++) {
                int off = (k / 3) * 16 + (k % 3);
                const ulonglong2 wA = *(const ulonglong2*)&sW[c][k][ty * 8];
                const ulonglong2 wB = *(const ulonglong2*)&sW[c][k][ty * 8 + 4];
                float f0 = sF[c][pb[0] + off];
                float f1 = sF[c][pb[1] + off];
                float f2 = sF[c][pb[2] + off];
                float f3 = sF[c][pb[3] + off];
                ull fd0, fd1, fd2, fd3;
                PACK2(fd0, f0, f0);
                PACK2(fd1, f1, f1);
                PACK2(fd2, f2, f2);
                PACK2(fd3, f3, f3);
                FMA2(acc[0][0], fd0, wA.x); FMA2(acc[0][1], fd0, wA.y);
                FMA2(acc[0][2], fd0, wB.x); FMA2(acc[0][3], fd0, wB.y);
                FMA2(acc[1][0], fd1, wA.x); FMA2(acc[1][1], fd1, wA.y);
                FMA2(acc[1][2], fd1, wB.x); FMA2(acc[1][3], fd1, wB.y);
                FMA2(acc[2][0], fd2, wA.x); FMA2(acc[2][1], fd2, wA.y);
                FMA2(acc[2][2], fd2, wB.x); FMA2(acc[2][3], fd2, wB.y);
                FMA2(acc[3][0], fd3, wA.x); FMA2(acc[3][1], fd3, wA.y);
                FMA2(acc[3][2], fd3, wB.x); FMA2(acc[3][3], fd3, wB.y);
            }
        }
    }

#pragma unroll
    for (int i = 0; i < 4; i++) {
        int p = tx + i * 64;
        if (p < P) {
            float2 v0 = *(float2*)&acc[i][0];
            float2 v1 = *(float2*)&acc[i][1];
            float2 v2 = *(float2*)&acc[i][2];
            float2 v3 = *(float2*)&acc[i][3];
            float* dst = &g_part[ks][(size_t)p * C_IN + n0 + ty * 8];
            *(float4*)dst       = make_float4(v0.x, v0.y, v1.x, v1.y);
            *(float4*)(dst + 4) = make_float4(v2.x, v2.y, v3.x, v3.y);
        }
    }
}

// ---------------- K1b: sum partials + bias + relu ----------------
__global__ void relu_sum(const float* __restrict__ bconv) {
    int i = blockIdx.x * 256 + threadIdx.x;
    if (i < P * C_IN) {
        float s = 0.f;
#pragma unroll
        for (int k = 0; k < KSPLIT; k++) s += g_part[k][i];
        s += bconv[i % C_IN];
        g_x[i] = fmaxf(s, 0.f);
    }
}

// ---------------- K2: cls/reg heads + box decode ----------------
__global__ void heads(const float* __restrict__ wcls, const float* __restrict__ bcls,
                      const float* __restrict__ wreg, const float* __restrict__ breg) {
    int gw   = (blockIdx.x * blockDim.x + threadIdx.x) >> 5;
    int lane = threadIdx.x & 31;
    if (gw >= NA) return;
    int p = gw / A, a = gw - p * A;

    const float* xr = &g_x[(size_t)p * C_IN];
    const float* wc = &wcls[(size_t)a * C_IN];
    const float* w0 = &wreg[(size_t)(a * 4 + 0) * C_IN];
    const float* w1 = &wreg[(size_t)(a * 4 + 1) * C_IN];
    const float* w2 = &wreg[(size_t)(a * 4 + 2) * C_IN];
    const float* w3 = &wreg[(size_t)(a * 4 + 3) * C_IN];

    float a0 = 0.f, a1 = 0.f, a2 = 0.f, a3 = 0.f, a4 = 0.f;
    for (int c = lane; c < C_IN; c += 32) {
        float xv = xr[c];
        a0 += xv * wc[c];
        a1 += xv * w0[c];
        a2 += xv * w1[c];
        a3 += xv * w2[c];
        a4 += xv * w3[c];
    }
#pragma unroll
    for (int o = 16; o > 0; o >>= 1) {
        a0 += __shfl_down_sync(0xffffffffu, a0, o);
        a1 += __shfl_down_sync(0xffffffffu, a1, o);
        a2 += __shfl_down_sync(0xffffffffu, a2, o);
        a3 += __shfl_down_sync(0xffffffffu, a3, o);
        a4 += __shfl_down_sync(0xffffffffu, a4, o);
    }
    if (lane == 0) {
        float s  = a0 + bcls[a];
        float dx = a1 + breg[a * 4 + 0];
        float dy = a2 + breg[a * 4 + 1];
        float dw = fminf(a3 + breg[a * 4 + 2], BBOX_CLIP);
        float dh = fminf(a4 + breg[a * 4 + 3], BBOX_CLIP);

        int y = p / HF, x = p - y * HF;
        float sx = x * 16.f, sy = y * 16.f;
        float ax0 = sx + c_base[a][0], ay0 = sy + c_base[a][1];
        float ax1 = sx + c_base[a][2], ay1 = sy + c_base[a][3];
        float aw = ax1 - ax0, ah = ay1 - ay0;
        float cx = ax0 + 0.5f * aw, cy = ay0 + 0.5f * ah;
        float pcx = dx * aw + cx, pcy = dy * ah + cy;
        float pw = expf(dw) * aw, ph = expf(dh) * ah;

        g_boxes[gw * 4 + 0] = pcx - 0.5f * pw;
        g_boxes[gw * 4 + 1] = pcy - 0.5f * ph;
        g_boxes[gw * 4 + 2] = pcx + 0.5f * pw;
        g_boxes[gw * 4 + 3] = pcy + 0.5f * ph;
        g_key[gw] = __fdiv_rn(1.f, 1.f + expf(-s));
    }
}

// ---------------- K3: parallel rank-sort + gather/clip/validity ----------------
// rank_i = #{j : key_j > key_i  or (key_j == key_i and j < i)}  (unique ranks,
// identical ordering to lax.top_k: descending, index-ascending ties)
__global__ void __launch_bounds__(128) ranksort() {
    __shared__ float sk[NA];
    int tid = threadIdx.x;
    int e = blockIdx.x * 128 + tid;
    for (int i = tid; i < NA; i += 128) sk[i] = g_key[i];
    __syncthreads();
    if (e >= NA) return;
    float k = sk[e];
    int rank = 0;
#pragma unroll 8
    for (int j = 0; j < NA; j++) {
        float kj = sk[j];
        rank += (kj > k) || (kj == k && j < e);
    }
    if (rank < NPRE) {
        float x1 = g_boxes[e * 4 + 0], y1 = g_boxes[e * 4 + 1];
        float x2 = g_boxes[e * 4 + 2], y2 = g_boxes[e * 4 + 3];
        x1 = fminf(fmaxf(x1, 0.f), IMGSZ);
        y1 = fminf(fmaxf(y1, 0.f), IMGSZ);
        x2 = fminf(fmaxf(x2, 0.f), IMGSZ);
        y2 = fminf(fmaxf(y2, 0.f), IMGSZ);
        g_tbox[rank * 4 + 0] = x1; g_tbox[rank * 4 + 1] = y1;
        g_tbox[rank * 4 + 2] = x2; g_tbox[rank * 4 + 3] = y2;
        g_tvalid[rank] = ((x2 - x1) >= MINSZ) && ((y2 - y1) >= MINSZ);
        g_tprob[rank]  = k;
    }
}

// ---------------- K4: IoU suppression bitmask ----------------
__global__ void __launch_bounds__(256) nms_mask() {
    __shared__ float sb[NPRE * 4];
    int ltid = threadIdx.y * 32 + threadIdx.x;
    for (int t = ltid; t < NPRE * 4; t += 256) sb[t] = g_tbox[t];
    __syncthreads();

    int i  = blockIdx.x * 8 + threadIdx.y;
    int tx = threadIdx.x;
    float ix1 = sb[i * 4 + 0], iy1 = sb[i * 4 + 1];
    float ix2 = sb[i * 4 + 2], iy2 = sb[i * 4 + 3];
    float iarea = (ix2 - ix1) * (iy2 - iy1);
    unsigned mword = 0;
    int jbase = tx * 32;
#pragma unroll 4
    for (int b = 0; b < 32; b++) {
        int j = jbase + b;
        if (j > i && j < NPRE) {
            float jx1 = sb[j * 4 + 0], jy1 = sb[j * 4 + 1];
            float jx2 = sb[j * 4 + 2], jy2 = sb[j * 4 + 3];
            float ww = fmaxf(0.f, fminf(ix2, jx2) - fmaxf(ix1, jx1));
            float hh = fmaxf(0.f, fminf(iy2, jy2) - fmaxf(iy1, jy1));
            float inter = ww * hh;
            float uni = iarea + (jx2 - jx1) * (jy2 - jy1) - inter;
            float iou = (uni > 0.f) ? __fdiv_rn(inter, uni) : 0.f;
            if (iou > NMS_TH) mword |= (1u << b);
        }
    }
    g_mask[i * 32 + tx] = mword;
}

// ---------------- K5: word-skipping NMS scan + output compaction ----------------
// warp 0 scans; lane L holds removed word L; only unsuppressed candidates visited.
__global__ void nms_scan(float* __restrict__ out) {
    extern __shared__ unsigned smask[];  // NPRE*32 words
    int tid = threadIdx.x;
    for (int t = tid; t < NPRE * 32; t += blockDim.x) smask[t] = g_mask[t];
    for (int t = tid; t < NOUT * 5; t += blockDim.x) out[t] = 0.f;
    __syncthreads();
    if (tid >= 32) return;
    int lane = tid;

    // valid bitmask, one word per lane
    unsigned vword = 0;
#pragma unroll
    for (int w = 0; w < 32; w++) {
        int idx = w * 32 + lane;
        int v = (idx < NPRE) ? g_tvalid[idx] : 0;
        unsigned bw = __ballot_sync(0xffffffffu, v);
        if (lane == w) vword = bw;
    }

    unsigned removed = 0;
    int count = 0;
    for (int w = 0; w < 32 && count < NOUT; w++) {
        unsigned pend = __shfl_sync(0xffffffffu, vword & ~removed, w);
        while (pend) {
            int b = __ffs(pend) - 1;
            pend &= pend - 1;
            int i = w * 32 + b;
            unsigned row = smask[i * 32 + lane];
            removed |= row;
            if (lane < 4)       out[count * 4 + lane]  = g_tbox[i * 4 + lane];
            else if (lane == 4) out[NOUT * 4 + count]  = g_tprob[i];
            count++;
            if (count == NOUT) break;
            pend &= ~__shfl_sync(0xffffffffu, row, w);  // in-word suppression
        }
    }
}

// ---------------- host launcher ----------------
extern "C" void kernel_launch(void* const* d_in, const int* in_sizes, int n_in,
                              void* d_out, int out_size) {
    const float* feature = (const float*)d_in[1];
    const float* w_conv  = (const float*)d_in[2];
    const float* b_conv  = (const float*)d_in[3];
    const float* w_cls   = (const float*)d_in[4];
    const float* b_cls   = (const float*)d_in[5];
    const float* w_reg   = (const float*)d_in[6];
    const float* b_reg   = (const float*)d_in[7];
    float* out = (float*)d_out;

    const float* feat = feature + C_IN;  // skip CLS token

    conv_part<<<NTILES * KSPLIT, 256>>>(feat, w_conv);
    relu_sum<<<(P * C_IN + 255) / 256, 256>>>(b_conv);
    heads<<<(NA * 32 + 255) / 256, 256>>>(w_cls, b_cls, w_reg, b_reg);
    ranksort<<<(NA + 127) / 128, 128>>>();
    nms_mask<<<NPRE / 8, dim3(32, 8)>>>();

    int smem_bytes = NPRE * 32 * 4;
    cudaFuncSetAttribute(nms_scan, cudaFuncAttributeMaxDynamicSharedMemorySize, smem_bytes);
    nms_scan<<<1, 128, smem_bytes>>>(out);
}

// round 3
// speedup vs baseline: 1.3905x; 1.1259x over previous
#include <cuda_runtime.h>
#include <math.h>

#define C_IN   768
#define HF     14
#define P      196
#define A      9
#define NA     1764
#define NPRE   1000
#define NOUT   300
#define IMGSZ  224.0f
#define NMS_TH 0.7f
#define MINSZ  16.0f
#define BBOX_CLIP 4.135166556742356f

// conv tiling: 144 blocks = 1 wave on 148 SMs
#define KSPLIT 12
#define KPER   64    // 768/12 input channels per block
#define KC     8     // smem chunk of input channels
#define NTILE  64    // out channels per block
#define NTILES 12    // 768/64

typedef unsigned long long ull;

// packed fp32x2 FMA (FFMA2) — 2x fp32 FMA throughput, exact fp32 per lane
#define FMA2(d, a, b) asm("fma.rn.f32x2 %0, %1, %2, %3;" : "=l"(d) : "l"(a), "l"(b), "l"(d))

// ---------------- device scratch ----------------
__device__ float g_part[KSPLIT][P * C_IN];
__device__ float g_key[NA];
__device__ float g_boxes[NA * 4];
__device__ float g_tbox[NPRE * 4];
__device__ float g_tprob[NPRE];
__device__ int   g_tvalid[NPRE];
__device__ unsigned g_mask[NPRE * 32];

// base anchors: a = ratio_idx*3 + scale_idx, ratios (0.5,1,2), scales (128,256,512)
__constant__ float c_base[9][4] = {
    {-91.f,  -45.f,  91.f,  45.f},
    {-181.f, -91.f,  181.f, 91.f},
    {-362.f, -181.f, 362.f, 181.f},
    {-64.f,  -64.f,  64.f,  64.f},
    {-128.f, -128.f, 128.f, 128.f},
    {-256.f, -256.f, 256.f, 256.f},
    {-45.f,  -91.f,  45.f,  91.f},
    {-91.f,  -181.f, 91.f,  181.f},
    {-181.f, -362.f, 181.f, 362.f}};

// ---------------- K1: 3x3 conv partial sums (implicit GEMM, FFMA2) ----------------
// 144 blocks x 256 threads; block = 64 out-ch x 196 px x 64 in-ch (one K-split).
// thread = 4 pixels x 16 out-channels (8 f32x2 pairs) register tile.
// feature tile stored pre-duplicated (float2 (v,v)) -> FFMA2 a-operand is one LDS.64.
__global__ void __launch_bounds__(256) conv_part(const float* __restrict__ feat,
                                                 const float* __restrict__ wconv) {
    int bx     = blockIdx.x;
    int ntile  = bx % NTILES;
    int ks     = bx / NTILES;
    int n0     = ntile * NTILE;
    int cbase0 = ks * KPER;
    int tid  = threadIdx.x;
    int tx   = tid & 63;   // pixel group
    int ty   = tid >> 6;   // out-channel group (0..3) -> och base ty*16
    int lane = tid & 31;
    int wrp  = tid >> 5;

    __shared__ __align__(16) float2 sFd[KC][256];        // 16KB: padded 16x16, dup pairs
    __shared__ __align__(16) float  sw[KC * 9][NTILE];   // 18KB

    ull acc[4][8];  // [pixel][och-pair]
#pragma unroll
    for (int i = 0; i < 4; i++)
#pragma unroll
        for (int j = 0; j < 8; j++) acc[i][j] = 0ULL;

    int pb[4];
#pragma unroll
    for (int i = 0; i < 4; i++) {
        int p = tx + i * 64;
        pb[i] = (p < P) ? ((p / HF) * 16 + (p % HF)) : 0;  // fallback (discarded)
    }

    for (int cc = 0; cc < KPER; cc += KC) {
        int cbase = cbase0 + cc;
        __syncthreads();
        // features: single pass, border zeros, duplicated pairs
        for (int i = tid; i < KC * 256; i += 256) {
            int c = i >> 8, s = i & 255;
            int sy = s >> 4, sx = s & 15;
            float v = 0.f;
            if ((unsigned)(sx - 1) < 14u && (unsigned)(sy - 1) < 14u)
                v = feat[(size_t)(cbase + c) * P + (sy - 1) * HF + (sx - 1)];
            sFd[c][s] = make_float2(v, v);
        }
        // weights: warp wrp covers n-half (wrp&1) x rk-quarter (wrp>>2? no: wrp>>1)
        {
            int n = ((wrp & 1) << 5) + lane;
            const float* src = wconv + (size_t)(n0 + n) * (C_IN * 9) + (size_t)cbase * 9;
            int rk0 = (wrp >> 1) * 18;
#pragma unroll
            for (int r = 0; r < 18; r++) sw[rk0 + r][n] = src[rk0 + r];
        }
        __syncthreads();

#pragma unroll 2
        for (int c = 0; c < KC; c++) {
#pragma unroll
            for (int k = 0; k < 9; k++) {
                const int off = (k / 3) * 16 + (k % 3);
                const ulonglong2* wp = (const ulonglong2*)&sw[c * 9 + k][ty * 16];
                ulonglong2 wA = wp[0], wB = wp[1], wC = wp[2], wD = wp[3];
                ull f0 = *(const ull*)&sFd[c][pb[0] + off];
                ull f1 = *(const ull*)&sFd[c][pb[1] + off];
                ull f2 = *(const ull*)&sFd[c][pb[2] + off];
                ull f3 = *(const ull*)&sFd[c][pb[3] + off];
                FMA2(acc[0][0], f0, wA.x); FMA2(acc[0][1], f0, wA.y);
                FMA2(acc[0][2], f0, wB.x); FMA2(acc[0][3], f0, wB.y);
                FMA2(acc[0][4], f0, wC.x); FMA2(acc[0][5], f0, wC.y);
                FMA2(acc[0][6], f0, wD.x); FMA2(acc[0][7], f0, wD.y);
                FMA2(acc[1][0], f1, wA.x); FMA2(acc[1][1], f1, wA.y);
                FMA2(acc[1][2], f1, wB.x); FMA2(acc[1][3], f1, wB.y);
                FMA2(acc[1][4], f1, wC.x); FMA2(acc[1][5], f1, wC.y);
                FMA2(acc[1][6], f1, wD.x); FMA2(acc[1][7], f1, wD.y);
                FMA2(acc[2][0], f2, wA.x); FMA2(acc[2][1], f2, wA.y);
                FMA2(acc[2][2], f2, wB.x); FMA2(acc[2][3], f2, wB.y);
                FMA2(acc[2][4], f2, wC.x); FMA2(acc[2][5], f2, wC.y);
                FMA2(acc[2][6], f2, wD.x); FMA2(acc[2][7], f2, wD.y);
                FMA2(acc[3][0], f3, wA.x); FMA2(acc[3][1], f3, wA.y);
                FMA2(acc[3][2], f3, wB.x); FMA2(acc[3][3], f3, wB.y);
                FMA2(acc[3][4], f3, wC.x); FMA2(acc[3][5], f3, wC.y);
                FMA2(acc[3][6], f3, wD.x); FMA2(acc[3][7], f3, wD.y);
            }
        }
    }

#pragma unroll
    for (int i = 0; i < 4; i++) {
        int p = tx + i * 64;
        if (p < P) {
            float* dst = &g_part[ks][(size_t)p * C_IN + n0 + ty * 16];
#pragma unroll
            for (int q = 0; q < 4; q++) {
                float2 lo = *(float2*)&acc[i][q * 2];
                float2 hi = *(float2*)&acc[i][q * 2 + 1];
                *(float4*)(dst + q * 4) = make_float4(lo.x, lo.y, hi.x, hi.y);
            }
        }
    }
}

// ---------------- K2: fused relu-sum + cls/reg heads + box decode ----------------
// one block per pixel (196 blocks x 256 threads)
__global__ void __launch_bounds__(256) heads(const float* __restrict__ bconv,
                                             const float* __restrict__ wcls,
                                             const float* __restrict__ bcls,
                                             const float* __restrict__ wreg,
                                             const float* __restrict__ breg) {
    int p = blockIdx.x;
    __shared__ float sx[C_IN];
    __shared__ float sdot[45];
    int tid = threadIdx.x;

    // relu(sum of K-split partials + bias)
    for (int c = tid; c < C_IN; c += 256) {
        float s = 0.f;
#pragma unroll
        for (int k = 0; k < KSPLIT; k++) s += g_part[k][(size_t)p * C_IN + c];
        sx[c] = fmaxf(s + bconv[c], 0.f);
    }
    __syncthreads();

    int wrp = tid >> 5, lane = tid & 31;
    for (int o = wrp; o < 45; o += 8) {
        int a = o / 5, r = o - a * 5;
        const float* wp = (r == 0) ? (wcls + (size_t)a * C_IN)
                                   : (wreg + (size_t)((a << 2) + r - 1) * C_IN);
        float accv = 0.f;
        for (int c = lane; c < C_IN; c += 32) accv += sx[c] * wp[c];
#pragma unroll
        for (int off = 16; off; off >>= 1) accv += __shfl_down_sync(0xffffffffu, accv, off);
        if (lane == 0) sdot[o] = accv;
    }
    __syncthreads();

    if (tid < A) {
        int a = tid;
        float s  = sdot[a * 5 + 0] + bcls[a];
        float dx = sdot[a * 5 + 1] + breg[a * 4 + 0];
        float dy = sdot[a * 5 + 2] + breg[a * 4 + 1];
        float dw = fminf(sdot[a * 5 + 3] + breg[a * 4 + 2], BBOX_CLIP);
        float dh = fminf(sdot[a * 5 + 4] + breg[a * 4 + 3], BBOX_CLIP);

        int y = p / HF, x = p - y * HF;
        float sxp = x * 16.f, syp = y * 16.f;
        float ax0 = sxp + c_base[a][0], ay0 = syp + c_base[a][1];
        float ax1 = sxp + c_base[a][2], ay1 = syp + c_base[a][3];
        float aw = ax1 - ax0, ah = ay1 - ay0;
        float cx = ax0 + 0.5f * aw, cy = ay0 + 0.5f * ah;
        float pcx = dx * aw + cx, pcy = dy * ah + cy;
        float pw = expf(dw) * aw, ph = expf(dh) * ah;

        int gw = p * A + a;
        g_boxes[gw * 4 + 0] = pcx - 0.5f * pw;
        g_boxes[gw * 4 + 1] = pcy - 0.5f * ph;
        g_boxes[gw * 4 + 2] = pcx + 0.5f * pw;
        g_boxes[gw * 4 + 3] = pcy + 0.5f * ph;
        g_key[gw] = __fdiv_rn(1.f, 1.f + expf(-s));
    }
}

// ---------------- K3: parallel rank-sort + gather/clip/validity ----------------
// rank_i = #{j : key_j > key_i or (key_j == key_i and j < i)} — identical ordering
// to lax.top_k. 111 blocks x 128 threads = 16 elements x 8 j-slices per block.
__global__ void __launch_bounds__(128) ranksort() {
    __shared__ float sk[NA];
    __shared__ int   partial[8][16];
    int tid = threadIdx.x;
    for (int i = tid; i < NA; i += 128) sk[i] = g_key[i];
    __syncthreads();

    int el = tid & 15, sl = tid >> 4;
    int e = blockIdx.x * 16 + el;
    float k = (e < NA) ? sk[e] : 0.f;
    int cnt = 0;
    int j0 = sl * 221, j1 = min(j0 + 221, NA);
#pragma unroll 8
    for (int j = j0; j < j1; j++) {
        float kj = sk[j];
        cnt += ((kj > k) || (kj == k && j < e)) ? 1 : 0;
    }
    partial[sl][el] = cnt;
    __syncthreads();

    if (sl == 0 && e < NA) {
        int rank = 0;
#pragma unroll
        for (int s2 = 0; s2 < 8; s2++) rank += partial[s2][el];
        if (rank < NPRE) {
            float x1 = g_boxes[e * 4 + 0], y1 = g_boxes[e * 4 + 1];
            float x2 = g_boxes[e * 4 + 2], y2 = g_boxes[e * 4 + 3];
            x1 = fminf(fmaxf(x1, 0.f), IMGSZ);
            y1 = fminf(fmaxf(y1, 0.f), IMGSZ);
            x2 = fminf(fmaxf(x2, 0.f), IMGSZ);
            y2 = fminf(fmaxf(y2, 0.f), IMGSZ);
            g_tbox[rank * 4 + 0] = x1; g_tbox[rank * 4 + 1] = y1;
            g_tbox[rank * 4 + 2] = x2; g_tbox[rank * 4 + 3] = y2;
            g_tvalid[rank] = ((x2 - x1) >= MINSZ) && ((y2 - y1) >= MINSZ);
            g_tprob[rank]  = k;
        }
    }
}

// ---------------- K4: IoU suppression bitmask ----------------
__global__ void __launch_bounds__(256) nms_mask() {
    __shared__ float sb[NPRE * 4];
    int ltid = threadIdx.y * 32 + threadIdx.x;
    for (int t = ltid; t < NPRE * 4; t += 256) sb[t] = g_tbox[t];
    __syncthreads();

    int i  = blockIdx.x * 8 + threadIdx.y;
    int tx = threadIdx.x;
    float ix1 = sb[i * 4 + 0], iy1 = sb[i * 4 + 1];
    float ix2 = sb[i * 4 + 2], iy2 = sb[i * 4 + 3];
    float iarea = (ix2 - ix1) * (iy2 - iy1);
    unsigned mword = 0;
    int jbase = tx * 32;
#pragma unroll 4
    for (int b = 0; b < 32; b++) {
        int j = jbase + b;
        if (j > i && j < NPRE) {
            float jx1 = sb[j * 4 + 0], jy1 = sb[j * 4 + 1];
            float jx2 = sb[j * 4 + 2], jy2 = sb[j * 4 + 3];
            float ww = fmaxf(0.f, fminf(ix2, jx2) - fmaxf(ix1, jx1));
            float hh = fmaxf(0.f, fminf(iy2, jy2) - fmaxf(iy1, jy1));
            float inter = ww * hh;
            float uni = iarea + (jx2 - jx1) * (jy2 - jy1) - inter;
            float iou = (uni > 0.f) ? __fdiv_rn(inter, uni) : 0.f;
            if (iou > NMS_TH) mword |= (1u << b);
        }
    }
    g_mask[i * 32 + tx] = mword;
}

// ---------------- K5: word-skipping NMS scan + output compaction ----------------
__global__ void nms_scan(float* __restrict__ out) {
    extern __shared__ unsigned smask[];  // NPRE*32 words
    int tid = threadIdx.x;
    for (int t = tid; t < NPRE * 32; t += blockDim.x) smask[t] = g_mask[t];
    for (int t = tid; t < NOUT * 5; t += blockDim.x) out[t] = 0.f;
    __syncthreads();
    if (tid >= 32) return;
    int lane = tid;

    // valid bitmask, one word per lane
    unsigned vword = 0;
#pragma unroll
    for (int w = 0; w < 32; w++) {
        int idx = w * 32 + lane;
        int v = (idx < NPRE) ? g_tvalid[idx] : 0;
        unsigned bw = __ballot_sync(0xffffffffu, v);
        if (lane == w) vword = bw;
    }

    unsigned removed = 0;
    int count = 0;
    for (int w = 0; w < 32 && count < NOUT; w++) {
        unsigned pend = __shfl_sync(0xffffffffu, vword & ~removed, w);
        while (pend) {
            int b = __ffs(pend) - 1;
            pend &= pend - 1;
            int i = w * 32 + b;
            unsigned row = smask[i * 32 + lane];
            removed |= row;
            if (lane < 4)       out[count * 4 + lane] = g_tbox[i * 4 + lane];
            else if (lane == 4) out[NOUT * 4 + count] = g_tprob[i];
            count++;
            if (count == NOUT) break;
            pend &= ~__shfl_sync(0xffffffffu, row, w);  // in-word suppression
        }
    }
}

// ---------------- host launcher ----------------
extern "C" void kernel_launch(void* const* d_in, const int* in_sizes, int n_in,
                              void* d_out, int out_size) {
    const float* feature = (const float*)d_in[1];
    const float* w_conv  = (const float*)d_in[2];
    const float* b_conv  = (const float*)d_in[3];
    const float* w_cls   = (const float*)d_in[4];
    const float* b_cls   = (const float*)d_in[5];
    const float* w_reg   = (const float*)d_in[6];
    const float* b_reg   = (const float*)d_in[7];
    float* out = (float*)d_out;

    const float* feat = feature + C_IN;  // skip CLS token

    conv_part<<<NTILES * KSPLIT, 256>>>(feat, w_conv);
    heads<<<P, 256>>>(b_conv, w_cls, b_cls, w_reg, b_reg);
    ranksort<<<(NA + 15) / 16, 128>>>();
    nms_mask<<<NPRE / 8, dim3(32, 8)>>>();

    int smem_bytes = NPRE * 32 * 4;
    cudaFuncSetAttribute(nms_scan, cudaFuncAttributeMaxDynamicSharedMemorySize, smem_bytes);
    nms_scan<<<1, 1024, smem_bytes>>>(out);
}

// round 6
// speedup vs baseline: 1.4433x; 1.0380x over previous
#include <cuda_runtime.h>
#include <math.h>

#define C_IN   768
#define HF     14
#define P      196
#define A      9
#define NA     1764
#define NPRE   1000
#define NOUT   300
#define IMGSZ  224.0f
#define NMS_TH 0.7f
#define MINSZ  16.0f
#define BBOX_CLIP 4.135166556742356f

// conv tiling: 144 blocks = 1 wave on 148 SMs
#define KSPLIT 12
#define KPER   64    // 768/12 input channels per block
#define KC     8     // smem chunk of input channels
#define NTILE  64    // out channels per block
#define NTILES 12    // 768/64

typedef unsigned long long ull;

// packed fp32x2 FMA (FFMA2) — 2x fp32 FMA throughput, exact fp32 per lane
#define FMA2(d, a, b) asm("fma.rn.f32x2 %0, %1, %2, %3;" : "=l"(d) : "l"(a), "l"(b), "l"(d))

// ---------------- device scratch ----------------
__device__ float g_part[KSPLIT][P * C_IN];
__device__ float g_key[NA];
__device__ float g_boxes[NA * 4];
__device__ __align__(16) float g_tbox[NPRE * 4];
__device__ float g_tprob[NPRE];
__device__ int   g_tvalid[NPRE];
__device__ unsigned g_mask[NPRE * 32];

// base anchors: a = ratio_idx*3 + scale_idx, ratios (0.5,1,2), scales (128,256,512)
__constant__ float c_base[9][4] = {
    {-91.f,  -45.f,  91.f,  45.f},
    {-181.f, -91.f,  181.f, 91.f},
    {-362.f, -181.f, 362.f, 181.f},
    {-64.f,  -64.f,  64.f,  64.f},
    {-128.f, -128.f, 128.f, 128.f},
    {-256.f, -256.f, 256.f, 256.f},
    {-45.f,  -91.f,  45.f,  91.f},
    {-91.f,  -181.f, 91.f,  181.f},
    {-181.f, -362.f, 181.f, 362.f}};

// ---------------- K1: 3x3 conv partial sums (implicit GEMM, FFMA2) ----------------
// 144 blocks x 256 threads; block = 64 out-ch x 196 px x 64 in-ch (one K-split).
// thread = 4 pixels x 16 out-channels (8 f32x2 pairs) register tile.
// feature tile stored pre-duplicated (float2 (v,v)) -> FFMA2 a-operand is one LDS.64.
__global__ void __launch_bounds__(256) conv_part(const float* __restrict__ feat,
                                                 const float* __restrict__ wconv) {
    int bx     = blockIdx.x;
    int ntile  = bx % NTILES;
    int ks     = bx / NTILES;
    int n0     = ntile * NTILE;
    int cbase0 = ks * KPER;
    int tid  = threadIdx.x;
    int tx   = tid & 63;   // pixel group
    int ty   = tid >> 6;   // out-channel group (0..3) -> och base ty*16
    int lane = tid & 31;
    int wrp  = tid >> 5;

    __shared__ __align__(16) float2 sFd[KC][256];        // 16KB: padded 16x16, dup pairs
    __shared__ __align__(16) float  sw[KC * 9][NTILE];   // 18KB

    ull acc[4][8];  // [pixel][och-pair]
#pragma unroll
    for (int i = 0; i < 4; i++)
#pragma unroll
        for (int j = 0; j < 8; j++) acc[i][j] = 0ULL;

    int pb[4];
#pragma unroll
    for (int i = 0; i < 4; i++) {
        int p = tx + i * 64;
        pb[i] = (p < P) ? ((p / HF) * 16 + (p % HF)) : 0;  // fallback (discarded)
    }

    for (int cc = 0; cc < KPER; cc += KC) {
        int cbase = cbase0 + cc;
        __syncthreads();
        // features: single pass, border zeros, duplicated pairs
        for (int i = tid; i < KC * 256; i += 256) {
            int c = i >> 8, s = i & 255;
            int sy = s >> 4, sx = s & 15;
            float v = 0.f;
            if ((unsigned)(sx - 1) < 14u && (unsigned)(sy - 1) < 14u)
                v = feat[(size_t)(cbase + c) * P + (sy - 1) * HF + (sx - 1)];
            sFd[c][s] = make_float2(v, v);
        }
        // weights
        {
            int n = ((wrp & 1) << 5) + lane;
            const float* src = wconv + (size_t)(n0 + n) * (C_IN * 9) + (size_t)cbase * 9;
            int rk0 = (wrp >> 1) * 18;
#pragma unroll
            for (int r = 0; r < 18; r++) sw[rk0 + r][n] = src[rk0 + r];
        }
        __syncthreads();

#pragma unroll 2
        for (int c = 0; c < KC; c++) {
#pragma unroll
            for (int k = 0; k < 9; k++) {
                const int off = (k / 3) * 16 + (k % 3);
                const ulonglong2* wp = (const ulonglong2*)&sw[c * 9 + k][ty * 16];
                ulonglong2 wA = wp[0], wB = wp[1], wC = wp[2], wD = wp[3];
                ull f0 = *(const ull*)&sFd[c][pb[0] + off];
                ull f1 = *(const ull*)&sFd[c][pb[1] + off];
                ull f2 = *(const ull*)&sFd[c][pb[2] + off];
                ull f3 = *(const ull*)&sFd[c][pb[3] + off];
                FMA2(acc[0][0], f0, wA.x); FMA2(acc[0][1], f0, wA.y);
                FMA2(acc[0][2], f0, wB.x); FMA2(acc[0][3], f0, wB.y);
                FMA2(acc[0][4], f0, wC.x); FMA2(acc[0][5], f0, wC.y);
                FMA2(acc[0][6], f0, wD.x); FMA2(acc[0][7], f0, wD.y);
                FMA2(acc[1][0], f1, wA.x); FMA2(acc[1][1], f1, wA.y);
                FMA2(acc[1][2], f1, wB.x); FMA2(acc[1][3], f1, wB.y);
                FMA2(acc[1][4], f1, wC.x); FMA2(acc[1][5], f1, wC.y);
                FMA2(acc[1][6], f1, wD.x); FMA2(acc[1][7], f1, wD.y);
                FMA2(acc[2][0], f2, wA.x); FMA2(acc[2][1], f2, wA.y);
                FMA2(acc[2][2], f2, wB.x); FMA2(acc[2][3], f2, wB.y);
                FMA2(acc[2][4], f2, wC.x); FMA2(acc[2][5], f2, wC.y);
                FMA2(acc[2][6], f2, wD.x); FMA2(acc[2][7], f2, wD.y);
                FMA2(acc[3][0], f3, wA.x); FMA2(acc[3][1], f3, wA.y);
                FMA2(acc[3][2], f3, wB.x); FMA2(acc[3][3], f3, wB.y);
                FMA2(acc[3][4], f3, wC.x); FMA2(acc[3][5], f3, wC.y);
                FMA2(acc[3][6], f3, wD.x); FMA2(acc[3][7], f3, wD.y);
            }
        }
    }

#pragma unroll
    for (int i = 0; i < 4; i++) {
        int p = tx + i * 64;
        if (p < P) {
            float* dst = &g_part[ks][(size_t)p * C_IN + n0 + ty * 16];
#pragma unroll
            for (int q = 0; q < 4; q++) {
                float2 lo = *(float2*)&acc[i][q * 2];
                float2 hi = *(float2*)&acc[i][q * 2 + 1];
                *(float4*)(dst + q * 4) = make_float4(lo.x, lo.y, hi.x, hi.y);
            }
        }
    }
}

// ---------------- K2: fused relu-sum + cls/reg heads + box decode ----------------
__global__ void __launch_bounds__(256) heads(const float* __restrict__ bconv,
                                             const float* __restrict__ wcls,
                                             const float* __restrict__ bcls,
                                             const float* __restrict__ wreg,
                                             const float* __restrict__ breg) {
    int p = blockIdx.x;
    __shared__ float sx[C_IN];
    __shared__ float sdot[45];
    int tid = threadIdx.x;

    for (int c = tid; c < C_IN; c += 256) {
        float s = 0.f;
#pragma unroll
        for (int k = 0; k < KSPLIT; k++) s += g_part[k][(size_t)p * C_IN + c];
        sx[c] = fmaxf(s + bconv[c], 0.f);
    }
    __syncthreads();

    int wrp = tid >> 5, lane = tid & 31;
    for (int o = wrp; o < 45; o += 8) {
        int a = o / 5, r = o - a * 5;
        const float* wp = (r == 0) ? (wcls + (size_t)a * C_IN)
                                   : (wreg + (size_t)((a << 2) + r - 1) * C_IN);
        float accv = 0.f;
        for (int c = lane; c < C_IN; c += 32) accv += sx[c] * wp[c];
#pragma unroll
        for (int off = 16; off; off >>= 1) accv += __shfl_down_sync(0xffffffffu, accv, off);
        if (lane == 0) sdot[o] = accv;
    }
    __syncthreads();

    if (tid < A) {
        int a = tid;
        float s  = sdot[a * 5 + 0] + bcls[a];
        float dx = sdot[a * 5 + 1] + breg[a * 4 + 0];
        float dy = sdot[a * 5 + 2] + breg[a * 4 + 1];
        float dw = fminf(sdot[a * 5 + 3] + breg[a * 4 + 2], BBOX_CLIP);
        float dh = fminf(sdot[a * 5 + 4] + breg[a * 4 + 3], BBOX_CLIP);

        int y = p / HF, x = p - y * HF;
        float sxp = x * 16.f, syp = y * 16.f;
        float ax0 = sxp + c_base[a][0], ay0 = syp + c_base[a][1];
        float ax1 = sxp + c_base[a][2], ay1 = syp + c_base[a][3];
        float aw = ax1 - ax0, ah = ay1 - ay0;
        float cx = ax0 + 0.5f * aw, cy = ay0 + 0.5f * ah;
        float pcx = dx * aw + cx, pcy = dy * ah + cy;
        float pw = expf(dw) * aw, ph = expf(dh) * ah;

        int gw = p * A + a;
        g_boxes[gw * 4 + 0] = pcx - 0.5f * pw;
        g_boxes[gw * 4 + 1] = pcy - 0.5f * ph;
        g_boxes[gw * 4 + 2] = pcx + 0.5f * pw;
        g_boxes[gw * 4 + 3] = pcy + 0.5f * ph;
        g_key[gw] = __fdiv_rn(1.f, 1.f + expf(-s));
    }
}

// ---------------- K3: parallel rank-sort + gather/clip/validity ----------------
__global__ void __launch_bounds__(128) ranksort() {
    __shared__ float sk[NA];
    __shared__ int   partial[8][16];
    int tid = threadIdx.x;
    for (int i = tid; i < NA; i += 128) sk[i] = g_key[i];
    __syncthreads();

    int el = tid & 15, sl = tid >> 4;
    int e = blockIdx.x * 16 + el;
    float k = (e < NA) ? sk[e] : 0.f;
    int cnt = 0;
    int j0 = sl * 221, j1 = min(j0 + 221, NA);
#pragma unroll 8
    for (int j = j0; j < j1; j++) {
        float kj = sk[j];
        cnt += ((kj > k) || (kj == k && j < e)) ? 1 : 0;
    }
    partial[sl][el] = cnt;
    __syncthreads();

    if (sl == 0 && e < NA) {
        int rank = 0;
#pragma unroll
        for (int s2 = 0; s2 < 8; s2++) rank += partial[s2][el];
        if (rank < NPRE) {
            float x1 = g_boxes[e * 4 + 0], y1 = g_boxes[e * 4 + 1];
            float x2 = g_boxes[e * 4 + 2], y2 = g_boxes[e * 4 + 3];
            x1 = fminf(fmaxf(x1, 0.f), IMGSZ);
            y1 = fminf(fmaxf(y1, 0.f), IMGSZ);
            x2 = fminf(fmaxf(x2, 0.f), IMGSZ);
            y2 = fminf(fmaxf(y2, 0.f), IMGSZ);
            g_tbox[rank * 4 + 0] = x1; g_tbox[rank * 4 + 1] = y1;
            g_tbox[rank * 4 + 2] = x2; g_tbox[rank * 4 + 3] = y2;
            g_tvalid[rank] = ((x2 - x1) >= MINSZ) && ((y2 - y1) >= MINSZ);
            g_tprob[rank]  = k;
        }
    }
}

// ---------------- K4: IoU suppression bitmask (ballot, conflict-free SoA) ----------------
// 125 blocks x 256 FLAT threads; warp wrp handles row i = blk*8 + wrp.
// For word w: lane = j - w*32 (contiguous SoA loads, zero bank conflicts);
// mask word built with one ballot; words entirely below i skipped (all zero).
__global__ void __launch_bounds__(256) nms_mask() {
    __shared__ float sx1[NPRE], sy1[NPRE], sx2[NPRE], sy2[NPRE];
    int tid = threadIdx.x;
    int lane = tid & 31, wrp = tid >> 5;
    for (int t = tid; t < NPRE; t += 256) {
        float4 b = *(const float4*)&g_tbox[t * 4];
        sx1[t] = b.x; sy1[t] = b.y; sx2[t] = b.z; sy2[t] = b.w;
    }
    __syncthreads();

    int i = blockIdx.x * 8 + wrp;
    float ix1 = sx1[i], iy1 = sy1[i], ix2 = sx2[i], iy2 = sy2[i];  // broadcast
    float iarea = (ix2 - ix1) * (iy2 - iy1);

    unsigned myword = 0;
    int w0 = i >> 5;  // words [0, w0) cover only j < i -> all zero
    for (int w = w0; w < 32; w++) {
        int j = (w << 5) + lane;
        bool sup = false;
        if (j > i && j < NPRE) {
            float jx1 = sx1[j], jy1 = sy1[j], jx2 = sx2[j], jy2 = sy2[j];
            float ww = fmaxf(0.f, fminf(ix2, jx2) - fmaxf(ix1, jx1));
            float hh = fmaxf(0.f, fminf(iy2, jy2) - fmaxf(iy1, jy1));
            float inter = ww * hh;
            float uni = iarea + (jx2 - jx1) * (jy2 - jy1) - inter;
            float iou = (uni > 0.f) ? __fdiv_rn(inter, uni) : 0.f;
            sup = iou > NMS_TH;
        }
        unsigned word = __ballot_sync(0xffffffffu, sup);
        if (lane == w) myword = word;
    }
    g_mask[i * 32 + lane] = myword;
}

// ---------------- K5: word-skipping NMS scan + output compaction ----------------
__global__ void nms_scan(float* __restrict__ out) {
    extern __shared__ unsigned smask[];  // NPRE*32 words
    int tid = threadIdx.x;
    for (int t = tid; t < NPRE * 32; t += blockDim.x) smask[t] = g_mask[t];
    for (int t = tid; t < NOUT * 5; t += blockDim.x) out[t] = 0.f;
    __syncthreads();
    if (tid >= 32) return;
    int lane = tid;

    unsigned vword = 0;
#pragma unroll
    for (int w = 0; w < 32; w++) {
        int idx = w * 32 + lane;
        int v = (idx < NPRE) ? g_tvalid[idx] : 0;
        unsigned bw = __ballot_sync(0xffffffffu, v);
        if (lane == w) vword = bw;
    }

    unsigned removed = 0;
    int count = 0;
    for (int w = 0; w < 32 && count < NOUT; w++) {
        unsigned pend = __shfl_sync(0xffffffffu, vword & ~removed, w);
        while (pend) {
            int b = __ffs(pend) - 1;
            pend &= pend - 1;
            int i = w * 32 + b;
            unsigned row = smask[i * 32 + lane];
            removed |= row;
            if (lane < 4)       out[count * 4 + lane] = g_tbox[i * 4 + lane];
            else if (lane == 4) out[NOUT * 4 + count] = g_tprob[i];
            count++;
            if (count == NOUT) break;
            pend &= ~__shfl_sync(0xffffffffu, row, w);  // in-word suppression
        }
    }
}

// ---------------- host launcher ----------------
extern "C" void kernel_launch(void* const* d_in, const int* in_sizes, int n_in,
                              void* d_out, int out_size) {
    const float* feature = (const float*)d_in[1];
    const float* w_conv  = (const float*)d_in[2];
    const float* b_conv  = (const float*)d_in[3];
    const float* w_cls   = (const float*)d_in[4];
    const float* b_cls   = (const float*)d_in[5];
    const float* w_reg   = (const float*)d_in[6];
    const float* b_reg   = (const float*)d_in[7];
    float* out = (float*)d_out;

    const float* feat = feature + C_IN;  // skip CLS token

    conv_part<<<NTILES * KSPLIT, 256>>>(feat, w_conv);
    heads<<<P, 256>>>(b_conv, w_cls, b_cls, w_reg, b_reg);
    ranksort<<<(NA + 15) / 16, 128>>>();
    nms_mask<<<NPRE / 8, 256>>>();   // FLAT 256 threads (matches kernel indexing)

    int smem_bytes = NPRE * 32 * 4;
    cudaFuncSetAttribute(nms_scan, cudaFuncAttributeMaxDynamicSharedMemorySize, smem_bytes);
    nms_scan<<<1, 1024, smem_bytes>>>(out);
}